// round 9
// baseline (speedup 1.0000x reference)
#include <cuda_runtime.h>
#include <cuda_bf16.h>
#include <cstdint>

#define NROWS 262144
#define DDIM  128

typedef unsigned long long u64;
typedef unsigned int u32;

// ---------------- device scratch (no allocations allowed) ----------------
__device__ float g_e[NROWS];
__device__ float g_sp[NROWS];
__device__ float g_expw[NROWS];
__device__ float g_S_part[2048];
__device__ float g_sumeE_part[2048 * 128];
__device__ float g_seMid[128 * 128];
__device__ float g_SMid[128];
__device__ float g_S;
__device__ float g_Cvec[128];
__device__ float g_bias[128];
__device__ __align__(16) float g_Wt[128 * 256];  // Wt[k][n] fp32
__device__ float g_gePart[2048 * 128];
__device__ float g_esumPart[2048];
__device__ float g_ge2[32 * 128];
__device__ float g_esum2[32];
__device__ float g_total;

// ---------------- packed f32x2 helpers (FFMA2 on sm_103) ----------------
__device__ __forceinline__ u64 pack2(float x, float y) {
    u64 r;
    asm("mov.b64 %0, {%1, %2};" : "=l"(r) : "f"(x), "f"(y));
    return r;
}
__device__ __forceinline__ void fma2(u64 &d, u64 a, u64 b) {
    asm("fma.rn.f32x2 %0, %1, %2, %0;" : "+l"(d) : "l"(a), "l"(b));
}
__device__ __forceinline__ void unpack2(u64 v, float &x, float &y) {
    asm("mov.b64 {%0, %1}, %2;" : "=f"(x), "=f"(y) : "l"(v));
}

// ---------------- smem layout for k3 (bytes) ----------------
#define FF_AS     0          // 128x128 fp32  (65536 B)
#define FF_BS     65536      // 128x256 fp32  (131072 B)
#define CVEC_OFF  196640
#define BIAS_OFF  197152
#define WVC_OFF   197664
#define ESM_OFF   198176
#define SPM_OFF   198688
#define WROW_OFF  199200
#define RED_OFF   199712     // 4*128*4 = 2048 used (room for more)
#define SM3_BYTES 208896

// ---------------- kernel 0: build Wt[k][n] = [W1^T | W2^T] (fp32) ----------------
__global__ void k0_wt(const float* __restrict__ W1, const float* __restrict__ W2) {
    int idx = blockIdx.x * 256 + threadIdx.x;   // 0..32767
    int k = idx >> 8;
    int n = idx & 255;
    g_Wt[idx] = (n < 128) ? W1[n * 128 + k] : W2[(n - 128) * 128 + k];
}

// ---------------- kernel 1: sp, s->e, partial S, partial sum_eE (smem-staged) ----------------
#define K1_STRIDE 129
#define K1_SVW    (128 * K1_STRIDE)
#define K1_EXP    (K1_SVW + 256)
#define K1_FLOATS (K1_EXP + 128)
#define K1_BYTES  (K1_FLOATS * 4)

__global__ __launch_bounds__(128) void k1_pass1(const float* __restrict__ E,
                                                const float* __restrict__ v,
                                                const float* __restrict__ wpa,
                                                const float* __restrict__ bpa) {
    extern __shared__ float s1[];
    float*  Es  = s1;
    float2* svw = (float2*)(s1 + K1_SVW);
    float*  es  = s1 + K1_EXP;

    int t = threadIdx.x;
    int rowbase = blockIdx.x * 128;
    const float4* E4 = (const float4*)E + rowbase * 32;

    #pragma unroll
    for (int i = 0; i < 32; i++) {
        int g4 = t + i * 128;
        int r = g4 >> 5, c4 = g4 & 31;
        float4 val = E4[g4];
        Es[(c4 * 4 + 0) * K1_STRIDE + r] = val.x;
        Es[(c4 * 4 + 1) * K1_STRIDE + r] = val.y;
        Es[(c4 * 4 + 2) * K1_STRIDE + r] = val.z;
        Es[(c4 * 4 + 3) * K1_STRIDE + r] = val.w;
    }
    svw[t] = make_float2(wpa[t], v[t]);
    __syncthreads();

    float sp = 0.f, s = 0.f;
    #pragma unroll 8
    for (int k = 0; k < 128; k++) {
        float ev = Es[k * K1_STRIDE + t];
        float2 c = svw[k];
        s  = fmaf(ev, c.x, s);
        sp = fmaf(ev, c.y, sp);
    }
    s += bpa[0];
    float e = expf(s);       // softmax shift-invariant; exponents tiny
    g_sp[rowbase + t] = sp;
    g_e[rowbase + t]  = e;
    es[t] = e;
    __syncthreads();

    float acc = 0.f;
    #pragma unroll 8
    for (int r = 0; r < 128; r++) acc = fmaf(es[r], Es[t * K1_STRIDE + r], acc);
    g_sumeE_part[blockIdx.x * 128 + t] = acc;

    if (t < 32) {
        float t4 = es[t] + es[t + 32] + es[t + 64] + es[t + 96];
        #pragma unroll
        for (int off = 16; off; off >>= 1) t4 += __shfl_xor_sync(0xffffffffu, t4, off);
        if (t == 0) g_S_part[blockIdx.x] = t4;
    }
}

// ---------------- kernel 2a: parallel fold 2048 partials -> 128 ----------------
__global__ __launch_bounds__(128) void k2a_reduce() {
    int b = blockIdx.x;      // 0..127
    int d = threadIdx.x;     // 0..127
    float p = 0.f;
    #pragma unroll
    for (int j = 0; j < 16; j++) p += g_sumeE_part[(b * 16 + j) * 128 + d];
    g_seMid[b * 128 + d] = p;
    if (d == 0) {
        float s = 0.f;
        #pragma unroll
        for (int j = 0; j < 16; j++) s += g_S_part[b * 16 + j];
        g_SMid[b] = s;
    }
}

// ---------------- kernel 2b: final fold (parallel); Cvec = W2 @ sum_eE; bias; S ----------
// 1024 threads: 8 threads per output everywhere; serial chains <=16.
__global__ __launch_bounds__(1024) void k2b_reduce(const float* __restrict__ W2,
                                                   const float* __restrict__ b_c1,
                                                   const float* __restrict__ b_c2) {
    __shared__ float red[1024];
    __shared__ float se[128];
    int tid = threadIdx.x;
    int d = tid & 127, h = tid >> 7;          // h = 0..7
    float p = 0.f;
    #pragma unroll
    for (int j = 0; j < 16; j++) p += g_seMid[(h * 16 + j) * 128 + d];
    red[h * 128 + d] = p;
    __syncthreads();
    if (tid < 128) {
        float s = 0.f;
        #pragma unroll
        for (int w = 0; w < 8; w++) s += red[w * 128 + tid];
        se[tid] = s;
    }
    if (tid >= 992) {    // last warp folds S in parallel with se fold
        int l = tid - 992;
        float s = g_SMid[l] + g_SMid[l + 32] + g_SMid[l + 64] + g_SMid[l + 96];
        #pragma unroll
        for (int off = 16; off; off >>= 1) s += __shfl_xor_sync(0xffffffffu, s, off);
        if (l == 0) g_S = s;
    }
    __syncthreads();
    // Cvec: 8 threads per row d2, 16 k's each, 8-lane segmented shuffle reduce
    int d2 = tid >> 3, sub = tid & 7;
    const float* wrow = W2 + d2 * 128 + sub * 16;
    const float* serow = se + sub * 16;
    float c = 0.f;
    #pragma unroll
    for (int k = 0; k < 16; k++) c = fmaf(wrow[k], serow[k], c);
    c += __shfl_xor_sync(0xffffffffu, c, 1);
    c += __shfl_xor_sync(0xffffffffu, c, 2);
    c += __shfl_xor_sync(0xffffffffu, c, 4);
    if (sub == 0) {
        g_Cvec[d2] = c;
        g_bias[d2] = b_c1[d2] + b_c2[d2];
    }
}

// ---------------- kernel 3: FFMA2 fused GEMM + PI + logits + block partials ----------------
// 2048 blocks x 512 threads; tile 128 rows x 256 cols; K=128.
// Thread (ty=wid, tx=lane) owns rows ty*8..+7, col pairs (64*np + 2*tx, +1), np=0..3.
__global__ __launch_bounds__(512, 1)
void k3_main(const float* __restrict__ E,
             const float* __restrict__ wvc,
             const float* __restrict__ bvcp) {
    extern __shared__ char smc[];
    float* As    = (float*)(smc + FF_AS);     // [128 m][128 k]
    float* Bs    = (float*)(smc + FF_BS);     // [128 k][256 n]
    float* cvecS = (float*)(smc + CVEC_OFF);
    float* biasS = (float*)(smc + BIAS_OFF);
    float* wvcS  = (float*)(smc + WVC_OFF);
    float* esm   = (float*)(smc + ESM_OFF);
    float* spm   = (float*)(smc + SPM_OFF);
    float* wrow  = (float*)(smc + WROW_OFF);
    float* red   = (float*)(smc + RED_OFF);

    int tid = threadIdx.x;
    int tx = tid & 31;
    int ty = tid >> 5;                 // 0..15
    int rowbase = blockIdx.x * 128;

    {
        const float4* E4 = (const float4*)E + rowbase * 32;
        float4* As4 = (float4*)As;
        #pragma unroll
        for (int it = 0; it < 8; it++) As4[tid + it * 512] = E4[tid + it * 512];
        const float4* Wt4 = (const float4*)g_Wt;
        float4* Bs4 = (float4*)Bs;
        #pragma unroll
        for (int it = 0; it < 16; it++) Bs4[tid + it * 512] = Wt4[tid + it * 512];
    }
    if (tid < 128) {
        cvecS[tid] = g_Cvec[tid];
        biasS[tid] = g_bias[tid];
        wvcS[tid]  = wvc[tid];
        esm[tid]   = g_e[rowbase + tid];
        spm[tid]   = g_sp[rowbase + tid];
    }
    float Sv  = g_S;
    float bvc = bvcp[0];
    __syncthreads();

    u64 acc[8][4];
    #pragma unroll
    for (int mm = 0; mm < 8; mm++)
        #pragma unroll
        for (int np = 0; np < 4; np++) acc[mm][np] = 0ull;

    const float* Arow = As + (ty * 8) * 128;
    #pragma unroll 2
    for (int k0 = 0; k0 < 128; k0 += 2) {
        float2 a2[8];
        #pragma unroll
        for (int mm = 0; mm < 8; mm++)
            a2[mm] = *(const float2*)(Arow + mm * 128 + k0);   // warp-broadcast
        const u64* b0p = (const u64*)(Bs) + (u64)k0 * 128 + tx;
        const u64* b1p = b0p + 128;
        u64 b0[4], b1[4];
        #pragma unroll
        for (int np = 0; np < 4; np++) { b0[np] = b0p[np * 32]; b1[np] = b1p[np * 32]; }
        #pragma unroll
        for (int mm = 0; mm < 8; mm++) {
            u64 ad = pack2(a2[mm].x, a2[mm].x);
            #pragma unroll
            for (int np = 0; np < 4; np++) fma2(acc[mm][np], ad, b0[np]);
        }
        #pragma unroll
        for (int mm = 0; mm < 8; mm++) {
            u64 ad = pack2(a2[mm].y, a2[mm].y);
            #pragma unroll
            for (int np = 0; np < 4; np++) fma2(acc[mm][np], ad, b1[np]);
        }
    }

    // register epilogue: a-col j = 64*np+2tx pairs with b-col j+128 at np+2 in same thread
    #pragma unroll
    for (int rr = 0; rr < 8; rr++) {
        int r = ty * 8 + rr;
        float e_i = esm[r];
        float inv = 1.0f / (Sv - e_i);
        float accp = 0.f;
        #pragma unroll
        for (int np = 0; np < 2; np++) {
            float ax, ay, bx, by;
            unpack2(acc[rr][np], ax, ay);
            unpack2(acc[rr][np + 2], bx, by);
            int j = 64 * np + 2 * tx;
            float hx = ax + (cvecS[j]     - e_i * bx) * inv + biasS[j];
            float hy = ay + (cvecS[j + 1] - e_i * by) * inv + biasS[j + 1];
            accp += fmaxf(hx, 0.f) * wvcS[j] + fmaxf(hy, 0.f) * wvcS[j + 1];
        }
        #pragma unroll
        for (int off = 16; off; off >>= 1) accp += __shfl_xor_sync(0xffffffffu, accp, off);
        if (tx == 0) {
            float lg = spm[r] + accp + bvc;
            float wv = expf(lg);
            wrow[r] = wv;
            g_expw[rowbase + r] = wv;
        }
    }
    __syncthreads();

    {
        int d = tid & 127;
        int grp = tid >> 7;          // 0..3 -> 32 rows each
        float g = 0.f;
        #pragma unroll 8
        for (int rr = 0; rr < 32; rr++) {
            int r = grp * 32 + rr;
            g = fmaf(wrow[r], As[r * 128 + d], g);
        }
        red[grp * 128 + d] = g;
    }
    __syncthreads();
    if (tid < 128)
        g_gePart[blockIdx.x * 128 + tid] =
            red[tid] + red[128 + tid] + red[256 + tid] + red[384 + tid];
    if (tid < 32) {
        float s2 = wrow[tid] + wrow[tid + 32] + wrow[tid + 64] + wrow[tid + 96];
        #pragma unroll
        for (int off = 16; off; off >>= 1) s2 += __shfl_xor_sync(0xffffffffu, s2, off);
        if (tid == 0) g_esumPart[blockIdx.x] = s2;
    }
}

// ---------------- kernel 4a: reduce 2048 block partials -> 32 ----------------
__global__ void k4a_reduce() {
    int b0 = blockIdx.x * 64;
    int d = threadIdx.x;    // 128 threads
    float g = 0.f;
    #pragma unroll 8
    for (int j = 0; j < 64; j++) g += g_gePart[(b0 + j) * 128 + d];
    g_ge2[blockIdx.x * 128 + d] = g;
    if (d == 0) {
        float s = 0.f;
        for (int j = 0; j < 64; j++) s += g_esumPart[b0 + j];
        g_esum2[blockIdx.x] = s;
    }
}

// ---------------- kernel 4b: final ge + total ----------------
__global__ void k4b_final(float* ge_out) {
    __shared__ float tot;
    int d = threadIdx.x;    // 128 threads
    float g = 0.f;
    #pragma unroll
    for (int c = 0; c < 32; c++) g += g_ge2[c * 128 + d];
    if (d < 32) {
        float t = g_esum2[d];
        #pragma unroll
        for (int off = 16; off; off >>= 1) t += __shfl_xor_sync(0xffffffffu, t, off);
        if (d == 0) { tot = t; g_total = t; }
    }
    __syncthreads();
    if (ge_out) ge_out[d] = g / tot;
}

// ---------------- kernel 5: attention weights ----------------
__global__ void k5_attn(float* __restrict__ attn_out) {
    int i = blockIdx.x * 1024 + threadIdx.x;
    attn_out[i] = g_expw[i] / g_total;
}

// ---------------- launcher ----------------
extern "C" void kernel_launch(void* const* d_in, const int* in_sizes, int n_in,
                              void* d_out, int out_size) {
    const float* E    = (const float*)d_in[0];
    const float* item = (const float*)d_in[1];
    const float* W1   = (const float*)d_in[2];
    const float* bc1  = (const float*)d_in[3];
    const float* W2   = (const float*)d_in[4];
    const float* bc2  = (const float*)d_in[5];
    const float* wpa  = (const float*)d_in[6];
    const float* bpa  = (const float*)d_in[7];
    const float* wvc  = (const float*)d_in[8];
    const float* bvc  = (const float*)d_in[9];

    float* out = (float*)d_out;
    float* ge_out = nullptr;
    float* attn_out = nullptr;
    if (out_size == NROWS + DDIM)      { ge_out = out; attn_out = out + DDIM; }
    else if (out_size == DDIM)         { ge_out = out; }
    else                               { attn_out = out; }

    cudaFuncSetAttribute(k1_pass1, cudaFuncAttributeMaxDynamicSharedMemorySize, K1_BYTES);
    cudaFuncSetAttribute(k3_main,  cudaFuncAttributeMaxDynamicSharedMemorySize, SM3_BYTES);

    k0_wt<<<128, 256>>>(W1, W2);
    k1_pass1<<<2048, 128, K1_BYTES>>>(E, item, wpa, bpa);
    k2a_reduce<<<128, 128>>>();
    k2b_reduce<<<1, 1024>>>(W2, bc1, bc2);
    k3_main<<<2048, 512, SM3_BYTES>>>(E, wvc, bvc);
    k4a_reduce<<<32, 128>>>();
    k4b_final<<<1, 128>>>(ge_out);
    if (attn_out) k5_attn<<<256, 1024>>>(attn_out);
}

// round 10
// speedup vs baseline: 1.0047x; 1.0047x over previous
#include <cuda_runtime.h>
#include <cuda_bf16.h>
#include <cstdint>

#define NROWS 262144
#define DDIM  128

typedef unsigned long long u64;
typedef unsigned int u32;

// ---------------- device scratch (no allocations allowed) ----------------
__device__ float g_e[NROWS];
__device__ float g_sp[NROWS];
__device__ float g_expw[NROWS];
__device__ float g_S_part[2048];
__device__ float g_sumeE_part[2048 * 128];
__device__ float g_seMid[128 * 128];
__device__ float g_SMid[128];
__device__ float g_S;
__device__ float g_Cvec[128];
__device__ float g_bias[128];
__device__ __align__(16) float g_Wt[128 * 256];  // Wt[k][n] fp32
__device__ float g_gePart[2048 * 128];
__device__ float g_esumPart[2048];
__device__ float g_ge2[32 * 128];
__device__ float g_esum2[32];
__device__ float g_total;
__device__ float g_invTotal;

// ---------------- packed f32x2 helpers (FFMA2 on sm_103) ----------------
__device__ __forceinline__ u64 pack2(float x, float y) {
    u64 r;
    asm("mov.b64 %0, {%1, %2};" : "=l"(r) : "f"(x), "f"(y));
    return r;
}
__device__ __forceinline__ void fma2(u64 &d, u64 a, u64 b) {
    asm("fma.rn.f32x2 %0, %1, %2, %0;" : "+l"(d) : "l"(a), "l"(b));
}
__device__ __forceinline__ void unpack2(u64 v, float &x, float &y) {
    asm("mov.b64 {%0, %1}, %2;" : "=f"(x), "=f"(y) : "l"(v));
}

// ---------------- smem layout for k3 (bytes) ----------------
#define FF_AS     0          // 128x128 fp32  (65536 B)
#define FF_BS     65536      // 128x256 fp32  (131072 B)
#define CVEC_OFF  196640
#define BIAS_OFF  197152
#define WVC_OFF   197664
#define ESM_OFF   198176
#define SPM_OFF   198688
#define WROW_OFF  199200
#define RED_OFF   199712     // 4*128*4 = 2048 used
#define SM3_BYTES 208896

// ---------------- kernel 0: build Wt[k][n] = [W1^T | W2^T] (fp32) ----------------
__global__ void k0_wt(const float* __restrict__ W1, const float* __restrict__ W2) {
    int idx = blockIdx.x * 256 + threadIdx.x;   // 0..32767
    int k = idx >> 8;
    int n = idx & 255;
    g_Wt[idx] = (n < 128) ? W1[n * 128 + k] : W2[(n - 128) * 128 + k];
}

// ---------------- kernel 1: sp, s->e, partial S, partial sum_eE (smem-staged) ----------------
#define K1_STRIDE 129
#define K1_SVW    (128 * K1_STRIDE)
#define K1_EXP    (K1_SVW + 256)
#define K1_FLOATS (K1_EXP + 128)
#define K1_BYTES  (K1_FLOATS * 4)

__global__ __launch_bounds__(128) void k1_pass1(const float* __restrict__ E,
                                                const float* __restrict__ v,
                                                const float* __restrict__ wpa,
                                                const float* __restrict__ bpa) {
    extern __shared__ float s1[];
    float*  Es  = s1;
    float2* svw = (float2*)(s1 + K1_SVW);
    float*  es  = s1 + K1_EXP;

    int t = threadIdx.x;
    int rowbase = blockIdx.x * 128;
    const float4* E4 = (const float4*)E + rowbase * 32;

    #pragma unroll
    for (int i = 0; i < 32; i++) {
        int g4 = t + i * 128;
        int r = g4 >> 5, c4 = g4 & 31;
        float4 val = E4[g4];
        Es[(c4 * 4 + 0) * K1_STRIDE + r] = val.x;
        Es[(c4 * 4 + 1) * K1_STRIDE + r] = val.y;
        Es[(c4 * 4 + 2) * K1_STRIDE + r] = val.z;
        Es[(c4 * 4 + 3) * K1_STRIDE + r] = val.w;
    }
    svw[t] = make_float2(wpa[t], v[t]);
    __syncthreads();

    float sp = 0.f, s = 0.f;
    #pragma unroll 8
    for (int k = 0; k < 128; k++) {
        float ev = Es[k * K1_STRIDE + t];
        float2 c = svw[k];
        s  = fmaf(ev, c.x, s);
        sp = fmaf(ev, c.y, sp);
    }
    s += bpa[0];
    float e = expf(s);       // softmax shift-invariant; exponents tiny
    g_sp[rowbase + t] = sp;
    g_e[rowbase + t]  = e;
    es[t] = e;
    __syncthreads();

    float acc = 0.f;
    #pragma unroll 8
    for (int r = 0; r < 128; r++) acc = fmaf(es[r], Es[t * K1_STRIDE + r], acc);
    g_sumeE_part[blockIdx.x * 128 + t] = acc;

    if (t < 32) {
        float t4 = es[t] + es[t + 32] + es[t + 64] + es[t + 96];
        #pragma unroll
        for (int off = 16; off; off >>= 1) t4 += __shfl_xor_sync(0xffffffffu, t4, off);
        if (t == 0) g_S_part[blockIdx.x] = t4;
    }
}

// ---------------- kernel 2a: parallel fold 2048 partials -> 128 ----------------
__global__ __launch_bounds__(128) void k2a_reduce() {
    int b = blockIdx.x;      // 0..127
    int d = threadIdx.x;     // 0..127
    float p = 0.f;
    #pragma unroll
    for (int j = 0; j < 16; j++) p += g_sumeE_part[(b * 16 + j) * 128 + d];
    g_seMid[b * 128 + d] = p;
    if (d == 0) {
        float s = 0.f;
        #pragma unroll
        for (int j = 0; j < 16; j++) s += g_S_part[b * 16 + j];
        g_SMid[b] = s;
    }
}

// ---------------- kernel 2b: final fold (parallel); Cvec = W2 @ sum_eE; bias; S ----------
__global__ __launch_bounds__(1024) void k2b_reduce(const float* __restrict__ W2,
                                                   const float* __restrict__ b_c1,
                                                   const float* __restrict__ b_c2) {
    __shared__ float red[1024];
    __shared__ float se[128];
    int tid = threadIdx.x;
    int d = tid & 127, h = tid >> 7;          // h = 0..7
    float p = 0.f;
    #pragma unroll
    for (int j = 0; j < 16; j++) p += g_seMid[(h * 16 + j) * 128 + d];
    red[h * 128 + d] = p;
    __syncthreads();
    if (tid < 128) {
        float s = 0.f;
        #pragma unroll
        for (int w = 0; w < 8; w++) s += red[w * 128 + tid];
        se[tid] = s;
    }
    if (tid >= 992) {    // last warp folds S in parallel with se fold
        int l = tid - 992;
        float s = g_SMid[l] + g_SMid[l + 32] + g_SMid[l + 64] + g_SMid[l + 96];
        #pragma unroll
        for (int off = 16; off; off >>= 1) s += __shfl_xor_sync(0xffffffffu, s, off);
        if (l == 0) g_S = s;
    }
    __syncthreads();
    int d2 = tid >> 3, sub = tid & 7;
    const float* wrow = W2 + d2 * 128 + sub * 16;
    const float* serow = se + sub * 16;
    float c = 0.f;
    #pragma unroll
    for (int k = 0; k < 16; k++) c = fmaf(wrow[k], serow[k], c);
    c += __shfl_xor_sync(0xffffffffu, c, 1);
    c += __shfl_xor_sync(0xffffffffu, c, 2);
    c += __shfl_xor_sync(0xffffffffu, c, 4);
    if (sub == 0) {
        g_Cvec[d2] = c;
        g_bias[d2] = b_c1[d2] + b_c2[d2];
    }
}

// ---------------- kernel 3: FFMA2 fused GEMM + PI + logits + block partials ----------------
// 2048 blocks x 512 threads; tile 128 rows x 256 cols; K=128.
// Thread (ty=wid, tx=lane) owns rows ty*8..+7, col pairs (64*np + 2*tx, +1), np=0..3.
__global__ __launch_bounds__(512, 1)
void k3_main(const float* __restrict__ E,
             const float* __restrict__ wvc,
             const float* __restrict__ bvcp) {
    extern __shared__ char smc[];
    float* As    = (float*)(smc + FF_AS);     // [128 m][128 k]
    float* Bs    = (float*)(smc + FF_BS);     // [128 k][256 n]
    float* cvecS = (float*)(smc + CVEC_OFF);
    float* biasS = (float*)(smc + BIAS_OFF);
    float* wvcS  = (float*)(smc + WVC_OFF);
    float* esm   = (float*)(smc + ESM_OFF);
    float* spm   = (float*)(smc + SPM_OFF);
    float* wrow  = (float*)(smc + WROW_OFF);
    float* red   = (float*)(smc + RED_OFF);

    int tid = threadIdx.x;
    int tx = tid & 31;
    int ty = tid >> 5;                 // 0..15
    int rowbase = blockIdx.x * 128;

    {
        const float4* E4 = (const float4*)E + rowbase * 32;
        float4* As4 = (float4*)As;
        #pragma unroll
        for (int it = 0; it < 8; it++) As4[tid + it * 512] = E4[tid + it * 512];
        const float4* Wt4 = (const float4*)g_Wt;
        float4* Bs4 = (float4*)Bs;
        #pragma unroll
        for (int it = 0; it < 16; it++) Bs4[tid + it * 512] = Wt4[tid + it * 512];
    }
    if (tid < 128) {
        cvecS[tid] = g_Cvec[tid];
        biasS[tid] = g_bias[tid];
        wvcS[tid]  = wvc[tid];
        esm[tid]   = g_e[rowbase + tid];
        spm[tid]   = g_sp[rowbase + tid];
    }
    float Sv  = g_S;
    float bvc = bvcp[0];
    __syncthreads();

    u64 acc[8][4];
    #pragma unroll
    for (int mm = 0; mm < 8; mm++)
        #pragma unroll
        for (int np = 0; np < 4; np++) acc[mm][np] = 0ull;

    const float* Arow = As + (ty * 8) * 128;
    #pragma unroll 2
    for (int k0 = 0; k0 < 128; k0 += 2) {
        float2 a2[8];
        #pragma unroll
        for (int mm = 0; mm < 8; mm++)
            a2[mm] = *(const float2*)(Arow + mm * 128 + k0);   // warp-broadcast
        const u64* b0p = (const u64*)(Bs) + (u64)k0 * 128 + tx;
        const u64* b1p = b0p + 128;
        u64 b0[4], b1[4];
        #pragma unroll
        for (int np = 0; np < 4; np++) { b0[np] = b0p[np * 32]; b1[np] = b1p[np * 32]; }
        #pragma unroll
        for (int mm = 0; mm < 8; mm++) {
            u64 ad = pack2(a2[mm].x, a2[mm].x);
            #pragma unroll
            for (int np = 0; np < 4; np++) fma2(acc[mm][np], ad, b0[np]);
        }
        #pragma unroll
        for (int mm = 0; mm < 8; mm++) {
            u64 ad = pack2(a2[mm].y, a2[mm].y);
            #pragma unroll
            for (int np = 0; np < 4; np++) fma2(acc[mm][np], ad, b1[np]);
        }
    }

    // register epilogue: a-col j = 64*np+2tx pairs with b-col j+128 at np+2 in same thread
    #pragma unroll
    for (int rr = 0; rr < 8; rr++) {
        int r = ty * 8 + rr;
        float e_i = esm[r];
        float inv = 1.0f / (Sv - e_i);
        float accp = 0.f;
        #pragma unroll
        for (int np = 0; np < 2; np++) {
            float ax, ay, bx, by;
            unpack2(acc[rr][np], ax, ay);
            unpack2(acc[rr][np + 2], bx, by);
            int j = 64 * np + 2 * tx;
            float hx = ax + (cvecS[j]     - e_i * bx) * inv + biasS[j];
            float hy = ay + (cvecS[j + 1] - e_i * by) * inv + biasS[j + 1];
            accp += fmaxf(hx, 0.f) * wvcS[j] + fmaxf(hy, 0.f) * wvcS[j + 1];
        }
        #pragma unroll
        for (int off = 16; off; off >>= 1) accp += __shfl_xor_sync(0xffffffffu, accp, off);
        if (tx == 0) {
            float lg = spm[r] + accp + bvc;
            float wv = expf(lg);
            wrow[r] = wv;
            g_expw[rowbase + r] = wv;
        }
    }
    __syncthreads();

    {
        int d = tid & 127;
        int grp = tid >> 7;          // 0..3 -> 32 rows each
        float g = 0.f;
        #pragma unroll 8
        for (int rr = 0; rr < 32; rr++) {
            int r = grp * 32 + rr;
            g = fmaf(wrow[r], As[r * 128 + d], g);
        }
        red[grp * 128 + d] = g;
    }
    __syncthreads();
    if (tid < 128)
        g_gePart[blockIdx.x * 128 + tid] =
            red[tid] + red[128 + tid] + red[256 + tid] + red[384 + tid];
    if (tid < 32) {
        float s2 = wrow[tid] + wrow[tid + 32] + wrow[tid + 64] + wrow[tid + 96];
        #pragma unroll
        for (int off = 16; off; off >>= 1) s2 += __shfl_xor_sync(0xffffffffu, s2, off);
        if (tid == 0) g_esumPart[blockIdx.x] = s2;
    }
}

// ---------------- kernel 4a: reduce 2048 block partials -> 32 ----------------
__global__ void k4a_reduce() {
    int b0 = blockIdx.x * 64;
    int d = threadIdx.x;    // 128 threads
    float g = 0.f;
    #pragma unroll 8
    for (int j = 0; j < 64; j++) g += g_gePart[(b0 + j) * 128 + d];
    g_ge2[blockIdx.x * 128 + d] = g;
    if (d == 0) {
        float s = 0.f;
        for (int j = 0; j < 64; j++) s += g_esumPart[b0 + j];
        g_esum2[blockIdx.x] = s;
    }
}

// ---------------- kernel 4b: final ge + total (also stores 1/total) ----------------
__global__ void k4b_final(float* ge_out) {
    __shared__ float tot;
    int d = threadIdx.x;    // 128 threads
    float g = 0.f;
    #pragma unroll
    for (int c = 0; c < 32; c++) g += g_ge2[c * 128 + d];
    if (d < 32) {
        float t = g_esum2[d];
        #pragma unroll
        for (int off = 16; off; off >>= 1) t += __shfl_xor_sync(0xffffffffu, t, off);
        if (d == 0) { tot = t; g_total = t; g_invTotal = 1.0f / t; }
    }
    __syncthreads();
    if (ge_out) ge_out[d] = g / tot;
}

// ---------------- kernel 5: attention weights ----------------
__global__ void k5_attn(float* __restrict__ attn_out) {
    int i = blockIdx.x * 1024 + threadIdx.x;
    attn_out[i] = g_expw[i] * g_invTotal;
}

// ---------------- launcher ----------------
extern "C" void kernel_launch(void* const* d_in, const int* in_sizes, int n_in,
                              void* d_out, int out_size) {
    const float* E    = (const float*)d_in[0];
    const float* item = (const float*)d_in[1];
    const float* W1   = (const float*)d_in[2];
    const float* bc1  = (const float*)d_in[3];
    const float* W2   = (const float*)d_in[4];
    const float* bc2  = (const float*)d_in[5];
    const float* wpa  = (const float*)d_in[6];
    const float* bpa  = (const float*)d_in[7];
    const float* wvc  = (const float*)d_in[8];
    const float* bvc  = (const float*)d_in[9];

    float* out = (float*)d_out;
    float* ge_out = nullptr;
    float* attn_out = nullptr;
    if (out_size == NROWS + DDIM)      { ge_out = out; attn_out = out + DDIM; }
    else if (out_size == DDIM)         { ge_out = out; }
    else                               { attn_out = out; }

    cudaFuncSetAttribute(k1_pass1, cudaFuncAttributeMaxDynamicSharedMemorySize, K1_BYTES);
    cudaFuncSetAttribute(k3_main,  cudaFuncAttributeMaxDynamicSharedMemorySize, SM3_BYTES);

    k0_wt<<<128, 256>>>(W1, W2);
    k1_pass1<<<2048, 128, K1_BYTES>>>(E, item, wpa, bpa);
    k2a_reduce<<<128, 128>>>();
    k2b_reduce<<<1, 1024>>>(W2, bc1, bc2);
    k3_main<<<2048, 512, SM3_BYTES>>>(E, wvc, bvc);
    k4a_reduce<<<32, 128>>>();
    k4b_final<<<1, 128>>>(ge_out);
    if (attn_out) k5_attn<<<256, 1024>>>(attn_out);
}